// round 3
// baseline (speedup 1.0000x reference)
#include <cuda_runtime.h>
#include <cuda_bf16.h>
#include <cstdint>

// Problem constants
#define BATCH 8
#define FIN   64
#define NPTS  4096
#define FOUT  64
#define KNN   20

// ---------------------------------------------------------------------------
// Device scratch (no allocations allowed)
// ---------------------------------------------------------------------------
__device__ float g_Yt[BATCH * NPTS * FOUT];                    // W2 . x_n
__device__ float g_Ct[BATCH * NPTS * FOUT];                    // (W1-W2).x_n + b
__device__ __align__(16) float g_sq[BATCH * NPTS];             // ||x_n||^2
__device__ int   g_idx[BATCH * NPTS * KNN];                    // knn indices
__device__ __align__(16) __nv_bfloat16 g_p[BATCH * NPTS * 128];// [hi(64)|lo(64)]

// ---------------------------------------------------------------------------
// Portable PTX helpers (sm_80-level: compile fine for compute_103)
// ---------------------------------------------------------------------------
__device__ __forceinline__ uint32_t smem_u32(const void* p) {
    uint32_t a;
    asm("{ .reg .u64 t; cvta.to.shared.u64 t, %1; cvt.u32.u64 %0, t; }" : "=r"(a) : "l"(p));
    return a;
}
__device__ __forceinline__ void ldsm_x4(uint32_t addr, uint32_t* r) {
    asm volatile("ldmatrix.sync.aligned.m8n8.x4.shared.b16 {%0,%1,%2,%3}, [%4];"
        : "=r"(r[0]), "=r"(r[1]), "=r"(r[2]), "=r"(r[3]) : "r"(addr));
}
__device__ __forceinline__ void mma16816(float* c, const uint32_t* a, const uint32_t* b) {
    asm volatile("mma.sync.aligned.m16n8k16.row.col.f32.bf16.bf16.f32 "
        "{%0,%1,%2,%3}, {%4,%5,%6,%7}, {%8,%9}, {%0,%1,%2,%3};"
        : "+f"(c[0]), "+f"(c[1]), "+f"(c[2]), "+f"(c[3])
        : "r"(a[0]), "r"(a[1]), "r"(a[2]), "r"(a[3]), "r"(b[0]), "r"(b[1]));
}
#define CP_ASYNC16(dst, src) \
    asm volatile("cp.async.cg.shared.global [%0], [%1], 16;" :: "r"(dst), "l"(src))
#define CP_COMMIT() asm volatile("cp.async.commit_group;" ::: "memory")
#define CP_WAIT1()  asm volatile("cp.async.wait_group 1;" ::: "memory")
#define CP_WAIT0()  asm volatile("cp.async.wait_group 0;" ::: "memory")

// ---------------------------------------------------------------------------
// Kernel 1: per-point features Yt/Ct, sq norms, bf16 hi/lo packing
// ---------------------------------------------------------------------------
__global__ __launch_bounds__(128) void k1_features(
    const float* __restrict__ x, const float* __restrict__ W,
    const float* __restrict__ bvec)
{
    __shared__ float W2s[64][64];
    __shared__ float Wds[64][64];
    __shared__ float bs[64];

    const int bb  = blockIdx.y;
    const int n0  = blockIdx.x * 128;
    const int tid = threadIdx.x;

    for (int idx = tid; idx < 64 * 64; idx += 128) {
        int f = idx >> 6, o = idx & 63;
        float w1 = W[o * 128 + f];
        float w2 = W[o * 128 + 64 + f];
        W2s[f][o] = w2;
        Wds[f][o] = w1 - w2;
    }
    if (tid < 64) bs[tid] = bvec[tid];
    __syncthreads();

    const float* xb = x + (size_t)bb * FIN * NPTS;
    const int n = n0 + tid;

    float xr[64];
#pragma unroll
    for (int f = 0; f < 64; ++f) xr[f] = xb[f * NPTS + n];

    float sq = 0.f;
#pragma unroll
    for (int f = 0; f < 64; ++f) sq = fmaf(xr[f], xr[f], sq);
    g_sq[bb * NPTS + n] = sq;

    // bf16 hi/lo split pack: g_p row = [hi(64) | lo(64)]
    {
        uint4* pdst = (uint4*)(g_p + ((size_t)(bb * NPTS + n)) * 128);
#pragma unroll
        for (int q = 0; q < 8; ++q) {
            __nv_bfloat162 a = __floats2bfloat162_rn(xr[q * 8 + 0], xr[q * 8 + 1]);
            __nv_bfloat162 b = __floats2bfloat162_rn(xr[q * 8 + 2], xr[q * 8 + 3]);
            __nv_bfloat162 c = __floats2bfloat162_rn(xr[q * 8 + 4], xr[q * 8 + 5]);
            __nv_bfloat162 d = __floats2bfloat162_rn(xr[q * 8 + 6], xr[q * 8 + 7]);
            pdst[q] = make_uint4(*(unsigned*)&a, *(unsigned*)&b, *(unsigned*)&c, *(unsigned*)&d);
        }
#pragma unroll
        for (int q = 0; q < 8; ++q) {
            float r[8];
#pragma unroll
            for (int e = 0; e < 8; ++e) {
                float xf = xr[q * 8 + e];
                r[e] = xf - __bfloat162float(__float2bfloat16(xf));
            }
            __nv_bfloat162 a = __floats2bfloat162_rn(r[0], r[1]);
            __nv_bfloat162 b = __floats2bfloat162_rn(r[2], r[3]);
            __nv_bfloat162 c = __floats2bfloat162_rn(r[4], r[5]);
            __nv_bfloat162 d = __floats2bfloat162_rn(r[6], r[7]);
            pdst[8 + q] = make_uint4(*(unsigned*)&a, *(unsigned*)&b, *(unsigned*)&c, *(unsigned*)&d);
        }
    }

    const size_t base = ((size_t)(bb * NPTS + n)) * 64;

#pragma unroll 1
    for (int half = 0; half < 2; ++half) {
        float ya[32], ca[32];
#pragma unroll
        for (int oo = 0; oo < 32; ++oo) { ya[oo] = 0.f; ca[oo] = bs[half * 32 + oo]; }

#pragma unroll 4
        for (int f = 0; f < 64; ++f) {
            float xf = xr[f];
#pragma unroll
            for (int oo = 0; oo < 32; oo += 4) {
                float4 w2 = *(const float4*)&W2s[f][half * 32 + oo];
                float4 wd = *(const float4*)&Wds[f][half * 32 + oo];
                ya[oo + 0] = fmaf(w2.x, xf, ya[oo + 0]);
                ya[oo + 1] = fmaf(w2.y, xf, ya[oo + 1]);
                ya[oo + 2] = fmaf(w2.z, xf, ya[oo + 2]);
                ya[oo + 3] = fmaf(w2.w, xf, ya[oo + 3]);
                ca[oo + 0] = fmaf(wd.x, xf, ca[oo + 0]);
                ca[oo + 1] = fmaf(wd.y, xf, ca[oo + 1]);
                ca[oo + 2] = fmaf(wd.z, xf, ca[oo + 2]);
                ca[oo + 3] = fmaf(wd.w, xf, ca[oo + 3]);
            }
        }
        float4* Yp = (float4*)(g_Yt + base + half * 32);
        float4* Cp = (float4*)(g_Ct + base + half * 32);
#pragma unroll
        for (int q = 0; q < 8; ++q) {
            Yp[q] = make_float4(ya[4 * q], ya[4 * q + 1], ya[4 * q + 2], ya[4 * q + 3]);
            Cp[q] = make_float4(ca[4 * q], ca[4 * q + 1], ca[4 * q + 2], ca[4 * q + 3]);
        }
    }
}

// ---------------------------------------------------------------------------
// Kernel 2: HMMA (mma.sync bf16) distance GEMM + streaming top-20
// grid 256 (8 batches x 32 row-blocks of 128), 256 threads, 8 warps (4x2)
// 3 K-passes: Ah.Bh + Al.Bh + Ah.Bl  (Al.Bl ~ 2^-18, dropped)
// ---------------------------------------------------------------------------
#define TNC 64                       // candidate cols per tile
#define NT  (NPTS / TNC)             // 64 tiles

// smem byte offsets
#define SM_A   0                     // Ah[128][64] 16KB, Al[128][64] 16KB
#define SM_B   32768                 // 2 bufs x (Bh 8KB + Bl 8KB) = 32KB
#define SM_SQ  65536                 // 2 bufs x 64 floats = 512B
#define SM_D   66048                 // Ds 128 x 65 floats = 33280B
#define SM_TOT (SM_D + 128 * 65 * 4) // 99328

__global__ __launch_bounds__(256, 2) void k2_knn(void)
{
    extern __shared__ char sm[];
    const uint32_t smem_base = smem_u32(sm);
    float* Ds = (float*)(sm + SM_D);

    const int tid  = threadIdx.x;
    const int wid  = tid >> 5;
    const int lane = tid & 31;
    const int wr   = wid & 3;        // warp row group (32 rows)
    const int wc   = wid >> 2;       // warp col group (32 cols)

    const int bb = blockIdx.x >> 5;
    const int n0 = (blockIdx.x & 31) * 128;

    const __nv_bfloat16* gp = g_p + (size_t)bb * NPTS * 128;

    // ---- load A panels (hi|lo) swizzled ----
    for (int idx = tid; idx < 128 * 16; idx += 256) {
        int r = idx >> 4, ch = idx & 15;
        uint4 v = *(const uint4*)(gp + (size_t)(n0 + r) * 128 + ch * 8);
        uint32_t pan = (ch < 8) ? 0u : 16384u;
        uint32_t c16 = ch & 7;
        *(uint4*)(sm + SM_A + pan + r * 128 + ((c16 ^ (r & 7)) << 4)) = v;
    }

    // ---- B tile loader (cp.async) ----
    auto loadB = [&](int t, int buf) {
        const __nv_bfloat16* src0 = gp + (size_t)t * TNC * 128;
        uint32_t dst0 = smem_base + SM_B + buf * 16384;
#pragma unroll
        for (int k = 0; k < 4; ++k) {
            int idx = tid + k * 256;             // 0..1023
            int r = idx >> 4, ch = idx & 15;
            uint32_t pan = (ch < 8) ? 0u : 8192u;
            uint32_t c16 = ch & 7;
            CP_ASYNC16(dst0 + pan + r * 128 + ((c16 ^ (r & 7)) << 4),
                       src0 + (size_t)r * 128 + ch * 8);
        }
        if (tid < 16)
            CP_ASYNC16(smem_base + SM_SQ + buf * 256 + tid * 16,
                       g_sq + bb * NPTS + t * TNC + tid * 4);
    };

    // ---- top-k state: 2 threads per row (column halves) ----
    float bestd[KNN];
    int   besti[KNN];
#pragma unroll
    for (int i = 0; i < KNN; ++i) { bestd[i] = 3.0e38f; besti[i] = 0; }
    float worst = 3.0e38f;
    const int rrow = tid & 127;          // owned row (local)
    const int half = tid >> 7;           // column half (0/1)
    const int nrow = n0 + rrow;          // global row in batch

    loadB(0, 0);
    CP_COMMIT();

#pragma unroll 1
    for (int t = 0; t < NT; ++t) {
        const int cur = t & 1;
        if (t + 1 < NT) { loadB(t + 1, (t + 1) & 1); CP_COMMIT(); CP_WAIT1(); }
        else            { CP_WAIT0(); }
        __syncthreads();                 // tile t resident (and A on t==0)

        // ---- GEMM: 3 passes x 4 k16 steps ----
        float acc[2][4][4];
#pragma unroll
        for (int mt = 0; mt < 2; ++mt)
#pragma unroll
            for (int nt = 0; nt < 4; ++nt)
#pragma unroll
                for (int e = 0; e < 4; ++e) acc[mt][nt][e] = 0.f;

        const uint32_t abase = smem_base + SM_A;
        const uint32_t bbase = smem_base + SM_B + cur * 16384;
#pragma unroll
        for (int pass = 0; pass < 3; ++pass) {
            const uint32_t apan = abase + ((pass == 1) ? 16384u : 0u);
            const uint32_t bpan = bbase + ((pass == 2) ? 8192u : 0u);
#pragma unroll
            for (int ks = 0; ks < 4; ++ks) {
                uint32_t a[2][4], b2[2][4];
#pragma unroll
                for (int mt = 0; mt < 2; ++mt) {
                    int row = wr * 32 + mt * 16 + (lane & 15);
                    int ch  = ks * 2 + (lane >> 4);
                    ldsm_x4(apan + row * 128 + ((ch ^ (row & 7)) << 4), a[mt]);
                }
#pragma unroll
                for (int g = 0; g < 2; ++g) {
                    int row = wc * 32 + g * 16 + (lane & 7) + ((lane >> 4) << 3);
                    int ch  = ks * 2 + ((lane >> 3) & 1);
                    ldsm_x4(bpan + row * 128 + ((ch ^ (row & 7)) << 4), b2[g]);
                }
#pragma unroll
                for (int mt = 0; mt < 2; ++mt)
#pragma unroll
                    for (int nt = 0; nt < 4; ++nt)
                        mma16816(acc[mt][nt], a[mt], &b2[nt >> 1][(nt & 1) * 2]);
            }
        }

        // ---- stage dot tile to smem (stride 65) ----
#pragma unroll
        for (int mt = 0; mt < 2; ++mt) {
            int row0 = wr * 32 + mt * 16 + (lane >> 2);
#pragma unroll
            for (int nt = 0; nt < 4; ++nt) {
                int col0 = wc * 32 + nt * 8 + 2 * (lane & 3);
                Ds[row0 * 65 + col0]           = acc[mt][nt][0];
                Ds[row0 * 65 + col0 + 1]       = acc[mt][nt][1];
                Ds[(row0 + 8) * 65 + col0]     = acc[mt][nt][2];
                Ds[(row0 + 8) * 65 + col0 + 1] = acc[mt][nt][3];
            }
        }
        __syncthreads();

        // ---- streaming top-k scan over owned 32 columns ----
        const float* dr  = Ds + rrow * 65 + half * 32;
        const float* sqt = (const float*)(sm + SM_SQ + cur * 256) + half * 32;
        const int mbase  = t * TNC + half * 32;
#pragma unroll 1
        for (int j = 0; j < 32; ++j) {
            float key = fmaf(-2.0f, dr[j], sqt[j]);
            int m = mbase + j;
            if (key < worst && m != nrow) {
                bool done = false;
                float nw = -3.0e38f;
#pragma unroll
                for (int i = 0; i < KNN; ++i) {
                    if (!done && bestd[i] == worst) {
                        bestd[i] = key; besti[i] = m; done = true;
                    }
                    if (bestd[i] > nw) nw = bestd[i];
                }
                worst = nw;
            }
        }
        __syncthreads();                 // Ds / sq reusable
    }

    // ---- merge the two half-lists per row ----
    if (tid >= 128) {
#pragma unroll
        for (int i = 0; i < KNN; ++i) {
            Ds[rrow * 65 + i]       = bestd[i];
            Ds[rrow * 65 + 20 + i]  = __int_as_float(besti[i]);
        }
    }
    __syncthreads();
    if (tid < 128) {
#pragma unroll 1
        for (int i = 0; i < KNN; ++i) {
            float key = Ds[rrow * 65 + i];
            int   m   = __float_as_int(Ds[rrow * 65 + 20 + i]);
            if (key < worst) {
                bool done = false;
                float nw = -3.0e38f;
#pragma unroll
                for (int q = 0; q < KNN; ++q) {
                    if (!done && bestd[q] == worst) {
                        bestd[q] = key; besti[q] = m; done = true;
                    }
                    if (bestd[q] > nw) nw = bestd[q];
                }
                worst = nw;
            }
        }
        size_t base = ((size_t)(bb * NPTS + nrow)) * KNN;
#pragma unroll
        for (int i = 0; i < KNN; ++i) g_idx[base + i] = besti[i];
    }
}

// ---------------------------------------------------------------------------
// Kernel 3: gather-max epilogue + transpose to [b][o][n]
// ---------------------------------------------------------------------------
__global__ __launch_bounds__(256) void k3_epilogue(float* __restrict__ out)
{
    __shared__ float outs[64][65];
    const int bb  = blockIdx.y;
    const int n0  = blockIdx.x * 64;
    const int tid = threadIdx.x;
    const int w    = tid >> 5;
    const int lane = tid & 31;

    const float* Y = g_Yt + (size_t)bb * NPTS * 64;
    const float* C = g_Ct + (size_t)bb * NPTS * 64;

#pragma unroll 1
    for (int s = 0; s < 8; ++s) {
        int nn = w * 8 + s;
        int n  = n0 + nn;
        int jj = 0;
        if (lane < KNN) jj = g_idx[((size_t)(bb * NPTS + n)) * KNN + lane];
        float m0v = -3.0e38f, m1v = -3.0e38f;
#pragma unroll
        for (int i = 0; i < KNN; ++i) {
            int j = __shfl_sync(0xffffffffu, jj, i);
            const float* yr = Y + (size_t)j * 64;
            m0v = fmaxf(m0v, yr[lane]);
            m1v = fmaxf(m1v, yr[lane + 32]);
        }
        outs[nn][lane]      = m0v + C[(size_t)n * 64 + lane];
        outs[nn][lane + 32] = m1v + C[(size_t)n * 64 + lane + 32];
    }
    __syncthreads();

    float* ob = out + (size_t)bb * FOUT * NPTS;
#pragma unroll
    for (int it = 0; it < 16; ++it) {
        int lin = it * 256 + tid;
        int o  = lin >> 6;
        int nn = lin & 63;
        ob[o * NPTS + n0 + nn] = outs[nn][o];
    }
}

// ---------------------------------------------------------------------------
extern "C" void kernel_launch(void* const* d_in, const int* in_sizes, int n_in,
                              void* d_out, int out_size)
{
    const float* x    = (const float*)d_in[0];
    const float* W    = (const float*)d_in[1];
    const float* bvec = (const float*)d_in[2];
    float* out        = (float*)d_out;

    cudaFuncSetAttribute(k2_knn, cudaFuncAttributeMaxDynamicSharedMemorySize, SM_TOT);

    k1_features<<<dim3(NPTS / 128, BATCH), 128>>>(x, W, bvec);
    k2_knn<<<BATCH * (NPTS / 128), 256, SM_TOT>>>();
    k3_epilogue<<<dim3(NPTS / 64, BATCH), 256>>>(out);
}

// round 4
// speedup vs baseline: 2.6551x; 2.6551x over previous
#include <cuda_runtime.h>
#include <cuda_bf16.h>
#include <cstdint>

// Problem constants
#define BATCH 8
#define FIN   64
#define NPTS  4096
#define FOUT  64
#define KNN   20

#define FULLMASK 0xffffffffu
#define BIGF 3.0e38f

// ---------------------------------------------------------------------------
// Device scratch (no allocations allowed)
// ---------------------------------------------------------------------------
__device__ float g_Yt[BATCH * NPTS * FOUT];                    // W2 . x_n
__device__ float g_Ct[BATCH * NPTS * FOUT];                    // (W1-W2).x_n + b
__device__ __align__(16) float g_sq[BATCH * NPTS];             // ||x_n||^2
__device__ int   g_idx[BATCH * NPTS * KNN];                    // knn indices
__device__ __align__(16) __nv_bfloat16 g_p[BATCH * NPTS * 128];// [hi(64)|lo(64)]

// ---------------------------------------------------------------------------
// Portable PTX helpers (sm_80-level: compile fine for compute_103)
// ---------------------------------------------------------------------------
__device__ __forceinline__ uint32_t smem_u32(const void* p) {
    uint32_t a;
    asm("{ .reg .u64 t; cvta.to.shared.u64 t, %1; cvt.u32.u64 %0, t; }" : "=r"(a) : "l"(p));
    return a;
}
__device__ __forceinline__ void ldsm_x4(uint32_t addr, uint32_t* r) {
    asm volatile("ldmatrix.sync.aligned.m8n8.x4.shared.b16 {%0,%1,%2,%3}, [%4];"
        : "=r"(r[0]), "=r"(r[1]), "=r"(r[2]), "=r"(r[3]) : "r"(addr));
}
__device__ __forceinline__ void mma16816(float* c, const uint32_t* a, const uint32_t* b) {
    asm volatile("mma.sync.aligned.m16n8k16.row.col.f32.bf16.bf16.f32 "
        "{%0,%1,%2,%3}, {%4,%5,%6,%7}, {%8,%9}, {%0,%1,%2,%3};"
        : "+f"(c[0]), "+f"(c[1]), "+f"(c[2]), "+f"(c[3])
        : "r"(a[0]), "r"(a[1]), "r"(a[2]), "r"(a[3]), "r"(b[0]), "r"(b[1]));
}
#define CP_ASYNC16(dst, src) \
    asm volatile("cp.async.cg.shared.global [%0], [%1], 16;" :: "r"(dst), "l"(src))
#define CP_COMMIT() asm volatile("cp.async.commit_group;" ::: "memory")
#define CP_WAIT1()  asm volatile("cp.async.wait_group 1;" ::: "memory")
#define CP_WAIT0()  asm volatile("cp.async.wait_group 0;" ::: "memory")

// ---------------------------------------------------------------------------
// Kernel 1: per-point features Yt/Ct, sq norms, bf16 hi/lo packing
// ---------------------------------------------------------------------------
__global__ __launch_bounds__(128) void k1_features(
    const float* __restrict__ x, const float* __restrict__ W,
    const float* __restrict__ bvec)
{
    __shared__ float W2s[64][64];
    __shared__ float Wds[64][64];
    __shared__ float bs[64];

    const int bb  = blockIdx.y;
    const int n0  = blockIdx.x * 128;
    const int tid = threadIdx.x;

    for (int idx = tid; idx < 64 * 64; idx += 128) {
        int f = idx >> 6, o = idx & 63;
        float w1 = W[o * 128 + f];
        float w2 = W[o * 128 + 64 + f];
        W2s[f][o] = w2;
        Wds[f][o] = w1 - w2;
    }
    if (tid < 64) bs[tid] = bvec[tid];
    __syncthreads();

    const float* xb = x + (size_t)bb * FIN * NPTS;
    const int n = n0 + tid;

    float xr[64];
#pragma unroll
    for (int f = 0; f < 64; ++f) xr[f] = xb[f * NPTS + n];

    float sq = 0.f;
#pragma unroll
    for (int f = 0; f < 64; ++f) sq = fmaf(xr[f], xr[f], sq);
    g_sq[bb * NPTS + n] = sq;

    // bf16 hi/lo split pack: g_p row = [hi(64) | lo(64)]
    {
        uint4* pdst = (uint4*)(g_p + ((size_t)(bb * NPTS + n)) * 128);
#pragma unroll
        for (int q = 0; q < 8; ++q) {
            __nv_bfloat162 a = __floats2bfloat162_rn(xr[q * 8 + 0], xr[q * 8 + 1]);
            __nv_bfloat162 b = __floats2bfloat162_rn(xr[q * 8 + 2], xr[q * 8 + 3]);
            __nv_bfloat162 c = __floats2bfloat162_rn(xr[q * 8 + 4], xr[q * 8 + 5]);
            __nv_bfloat162 d = __floats2bfloat162_rn(xr[q * 8 + 6], xr[q * 8 + 7]);
            pdst[q] = make_uint4(*(unsigned*)&a, *(unsigned*)&b, *(unsigned*)&c, *(unsigned*)&d);
        }
#pragma unroll
        for (int q = 0; q < 8; ++q) {
            float r[8];
#pragma unroll
            for (int e = 0; e < 8; ++e) {
                float xf = xr[q * 8 + e];
                r[e] = xf - __bfloat162float(__float2bfloat16(xf));
            }
            __nv_bfloat162 a = __floats2bfloat162_rn(r[0], r[1]);
            __nv_bfloat162 b = __floats2bfloat162_rn(r[2], r[3]);
            __nv_bfloat162 c = __floats2bfloat162_rn(r[4], r[5]);
            __nv_bfloat162 d = __floats2bfloat162_rn(r[6], r[7]);
            pdst[8 + q] = make_uint4(*(unsigned*)&a, *(unsigned*)&b, *(unsigned*)&c, *(unsigned*)&d);
        }
    }

    const size_t base = ((size_t)(bb * NPTS + n)) * 64;

#pragma unroll 1
    for (int half = 0; half < 2; ++half) {
        float ya[32], ca[32];
#pragma unroll
        for (int oo = 0; oo < 32; ++oo) { ya[oo] = 0.f; ca[oo] = bs[half * 32 + oo]; }

#pragma unroll 4
        for (int f = 0; f < 64; ++f) {
            float xf = xr[f];
#pragma unroll
            for (int oo = 0; oo < 32; oo += 4) {
                float4 w2 = *(const float4*)&W2s[f][half * 32 + oo];
                float4 wd = *(const float4*)&Wds[f][half * 32 + oo];
                ya[oo + 0] = fmaf(w2.x, xf, ya[oo + 0]);
                ya[oo + 1] = fmaf(w2.y, xf, ya[oo + 1]);
                ya[oo + 2] = fmaf(w2.z, xf, ya[oo + 2]);
                ya[oo + 3] = fmaf(w2.w, xf, ya[oo + 3]);
                ca[oo + 0] = fmaf(wd.x, xf, ca[oo + 0]);
                ca[oo + 1] = fmaf(wd.y, xf, ca[oo + 1]);
                ca[oo + 2] = fmaf(wd.z, xf, ca[oo + 2]);
                ca[oo + 3] = fmaf(wd.w, xf, ca[oo + 3]);
            }
        }
        float4* Yp = (float4*)(g_Yt + base + half * 32);
        float4* Cp = (float4*)(g_Ct + base + half * 32);
#pragma unroll
        for (int q = 0; q < 8; ++q) {
            Yp[q] = make_float4(ya[4 * q], ya[4 * q + 1], ya[4 * q + 2], ya[4 * q + 3]);
            Cp[q] = make_float4(ca[4 * q], ca[4 * q + 1], ca[4 * q + 2], ca[4 * q + 3]);
        }
    }
}

// ---------------------------------------------------------------------------
// Kernel 2: HMMA distance GEMM + WARP-COOPERATIVE top-20 (shuffle-shift insert)
// grid 256 (8 batches x 32 row-blocks of 128), 256 threads, 8 warps (4x2)
// 4 K-passes: Ah.Bh + Al.Bh + Ah.Bl + Al.Bl (full split-bf16, ~fp32 exact)
// Selection: warp w owns rows [w*16, w*16+16); top-20 list held across lanes
// 0..19 (sorted ascending, lane 19 = worst). Insert = shuffle-shift (~9 instr).
// ---------------------------------------------------------------------------
#define TNC 64                       // candidate cols per tile
#define NT  (NPTS / TNC)             // 64 tiles

// smem byte offsets
#define SM_A   0                     // Ah[128][64] 16KB, Al[128][64] 16KB
#define SM_B   32768                 // 2 bufs x (Bh 8KB + Bl 8KB) = 32KB
#define SM_SQ  65536                 // 2 bufs x 64 floats = 512B
#define SM_D   66048                 // Ds 128 x 65 floats = 33280B
#define SM_TOT (SM_D + 128 * 65 * 4) // 99328

__global__ __launch_bounds__(256, 2) void k2_knn(void)
{
    extern __shared__ char sm[];
    const uint32_t smem_base = smem_u32(sm);
    float* Ds = (float*)(sm + SM_D);

    const int tid  = threadIdx.x;
    const int wid  = tid >> 5;
    const int lane = tid & 31;
    const int wr   = wid & 3;        // warp row group (32 rows) for GEMM
    const int wc   = wid >> 2;       // warp col group (32 cols) for GEMM

    const int bb = blockIdx.x >> 5;
    const int n0 = (blockIdx.x & 31) * 128;

    const __nv_bfloat16* gp = g_p + (size_t)bb * NPTS * 128;

    // ---- load A panels (hi|lo) swizzled ----
    for (int idx = tid; idx < 128 * 16; idx += 256) {
        int r = idx >> 4, ch = idx & 15;
        uint4 v = *(const uint4*)(gp + (size_t)(n0 + r) * 128 + ch * 8);
        uint32_t pan = (ch < 8) ? 0u : 16384u;
        uint32_t c16 = ch & 7;
        *(uint4*)(sm + SM_A + pan + r * 128 + ((c16 ^ (r & 7)) << 4)) = v;
    }

    // ---- B tile loader (cp.async) ----
    auto loadB = [&](int t, int buf) {
        const __nv_bfloat16* src0 = gp + (size_t)t * TNC * 128;
        uint32_t dst0 = smem_base + SM_B + buf * 16384;
#pragma unroll
        for (int k = 0; k < 4; ++k) {
            int idx = tid + k * 256;             // 0..1023
            int r = idx >> 4, ch = idx & 15;
            uint32_t pan = (ch < 8) ? 0u : 8192u;
            uint32_t c16 = ch & 7;
            CP_ASYNC16(dst0 + pan + r * 128 + ((c16 ^ (r & 7)) << 4),
                       src0 + (size_t)r * 128 + ch * 8);
        }
        if (tid < 16)
            CP_ASYNC16(smem_base + SM_SQ + buf * 256 + tid * 16,
                       g_sq + bb * NPTS + t * TNC + tid * 4);
    };

    // ---- selection state: warp owns 16 rows; list across lanes 0..19 ----
    float lv[16];                        // lane's slot value for each owned row
    int   li[16];                        // lane's slot index
#pragma unroll
    for (int r = 0; r < 16; ++r) { lv[r] = BIGF; li[r] = 0; }
    const int srow0 = wid * 16;          // first owned row (local)

    loadB(0, 0);
    CP_COMMIT();

#pragma unroll 1
    for (int t = 0; t < NT; ++t) {
        const int cur = t & 1;
        if (t + 1 < NT) { loadB(t + 1, (t + 1) & 1); CP_COMMIT(); CP_WAIT1(); }
        else            { CP_WAIT0(); }
        __syncthreads();                 // tile t resident (and A on t==0)

        // ---- GEMM: 4 passes x 4 k16 steps ----
        float acc[2][4][4];
#pragma unroll
        for (int mt = 0; mt < 2; ++mt)
#pragma unroll
            for (int nt = 0; nt < 4; ++nt)
#pragma unroll
                for (int e = 0; e < 4; ++e) acc[mt][nt][e] = 0.f;

        const uint32_t abase = smem_base + SM_A;
        const uint32_t bbase = smem_base + SM_B + cur * 16384;
#pragma unroll
        for (int pass = 0; pass < 4; ++pass) {
            const uint32_t apan = abase + ((pass & 1) ? 16384u : 0u);
            const uint32_t bpan = bbase + ((pass & 2) ? 8192u : 0u);
#pragma unroll
            for (int ks = 0; ks < 4; ++ks) {
                uint32_t a[2][4], b2[2][4];
#pragma unroll
                for (int mt = 0; mt < 2; ++mt) {
                    int row = wr * 32 + mt * 16 + (lane & 15);
                    int ch  = ks * 2 + (lane >> 4);
                    ldsm_x4(apan + row * 128 + ((ch ^ (row & 7)) << 4), a[mt]);
                }
#pragma unroll
                for (int g = 0; g < 2; ++g) {
                    int row = wc * 32 + g * 16 + (lane & 7) + ((lane >> 4) << 3);
                    int ch  = ks * 2 + ((lane >> 3) & 1);
                    ldsm_x4(bpan + row * 128 + ((ch ^ (row & 7)) << 4), b2[g]);
                }
#pragma unroll
                for (int mt = 0; mt < 2; ++mt)
#pragma unroll
                    for (int nt = 0; nt < 4; ++nt)
                        mma16816(acc[mt][nt], a[mt], &b2[nt >> 1][(nt & 1) * 2]);
            }
        }

        // ---- stage dot tile to smem (stride 65) ----
#pragma unroll
        for (int mt = 0; mt < 2; ++mt) {
            int row0 = wr * 32 + mt * 16 + (lane >> 2);
#pragma unroll
            for (int nt = 0; nt < 4; ++nt) {
                int col0 = wc * 32 + nt * 8 + 2 * (lane & 3);
                Ds[row0 * 65 + col0]           = acc[mt][nt][0];
                Ds[row0 * 65 + col0 + 1]       = acc[mt][nt][1];
                Ds[(row0 + 8) * 65 + col0]     = acc[mt][nt][2];
                Ds[(row0 + 8) * 65 + col0 + 1] = acc[mt][nt][3];
            }
        }
        __syncthreads();

        // ---- warp-cooperative top-20 over this tile's 64 candidate cols ----
        const float* sqt = (const float*)(sm + SM_SQ + cur * 256);
        const float sq0 = sqt[lane];
        const float sq1 = sqt[32 + lane];
        const int   m0g = t * TNC + lane;          // this lane's candidate ids
        const int   m1g = t * TNC + 32 + lane;

#pragma unroll
        for (int r = 0; r < 16; ++r) {
            const int row   = srow0 + r;
            const int nrowr = n0 + row;
            float k0 = fmaf(-2.0f, Ds[row * 65 + lane],      sq0);
            float k1 = fmaf(-2.0f, Ds[row * 65 + 32 + lane], sq1);
            if (m0g == nrowr) k0 = BIGF;           // self-exclusion
            if (m1g == nrowr) k1 = BIGF;

            float w = __shfl_sync(FULLMASK, lv[r], 19);   // current worst

#pragma unroll
            for (int pass = 0; pass < 2; ++pass) {
                const float kk = pass ? k1 : k0;
                const int   mm = pass ? m1g : m0g;
                unsigned b = __ballot_sync(FULLMASK, kk < w);
                while (b) {
                    const int s = __ffs(b) - 1;
                    b &= b - 1;
                    const float key = __shfl_sync(FULLMASK, kk, s);
                    const int   kid = __shfl_sync(FULLMASK, mm, s);
                    if (key < w) {
                        // shuffle-shift sorted insert (ascending, lane19 worst)
                        const float vprev = __shfl_up_sync(FULLMASK, lv[r], 1);
                        const int   iprev = __shfl_up_sync(FULLMASK, li[r], 1);
                        const bool pv    = lv[r] > key;
                        const bool pprev = (lane == 0) ? false : (vprev > key);
                        lv[r] = pv ? (pprev ? vprev : key) : lv[r];
                        li[r] = pv ? (pprev ? iprev : kid) : li[r];
                        w = __shfl_sync(FULLMASK, lv[r], 19);
                    }
                }
            }
        }
        __syncthreads();                 // Ds / sq reusable
    }

    // ---- write neighbor indices ----
#pragma unroll
    for (int r = 0; r < 16; ++r) {
        const int row = srow0 + r;
        if (lane < KNN)
            g_idx[((size_t)(bb * NPTS + n0 + row)) * KNN + lane] = li[r];
    }
}

// ---------------------------------------------------------------------------
// Kernel 3: gather-max epilogue + transpose to [b][o][n]
// ---------------------------------------------------------------------------
__global__ __launch_bounds__(256) void k3_epilogue(float* __restrict__ out)
{
    __shared__ float outs[64][65];
    const int bb  = blockIdx.y;
    const int n0  = blockIdx.x * 64;
    const int tid = threadIdx.x;
    const int w    = tid >> 5;
    const int lane = tid & 31;

    const float* Y = g_Yt + (size_t)bb * NPTS * 64;
    const float* C = g_Ct + (size_t)bb * NPTS * 64;

#pragma unroll 1
    for (int s = 0; s < 8; ++s) {
        int nn = w * 8 + s;
        int n  = n0 + nn;
        int jj = 0;
        if (lane < KNN) jj = g_idx[((size_t)(bb * NPTS + n)) * KNN + lane];
        float m0v = -3.0e38f, m1v = -3.0e38f;
#pragma unroll
        for (int i = 0; i < KNN; ++i) {
            int j = __shfl_sync(0xffffffffu, jj, i);
            const float* yr = Y + (size_t)j * 64;
            m0v = fmaxf(m0v, yr[lane]);
            m1v = fmaxf(m1v, yr[lane + 32]);
        }
        outs[nn][lane]      = m0v + C[(size_t)n * 64 + lane];
        outs[nn][lane + 32] = m1v + C[(size_t)n * 64 + lane + 32];
    }
    __syncthreads();

    float* ob = out + (size_t)bb * FOUT * NPTS;
#pragma unroll
    for (int it = 0; it < 16; ++it) {
        int lin = it * 256 + tid;
        int o  = lin >> 6;
        int nn = lin & 63;
        ob[o * NPTS + n0 + nn] = outs[nn][o];
    }
}

// ---------------------------------------------------------------------------
extern "C" void kernel_launch(void* const* d_in, const int* in_sizes, int n_in,
                              void* d_out, int out_size)
{
    const float* x    = (const float*)d_in[0];
    const float* W    = (const float*)d_in[1];
    const float* bvec = (const float*)d_in[2];
    float* out        = (float*)d_out;

    cudaFuncSetAttribute(k2_knn, cudaFuncAttributeMaxDynamicSharedMemorySize, SM_TOT);

    k1_features<<<dim3(NPTS / 128, BATCH), 128>>>(x, W, bvec);
    k2_knn<<<BATCH * (NPTS / 128), 256, SM_TOT>>>();
    k3_epilogue<<<dim3(NPTS / 64, BATCH), 256>>>(out);
}

// round 5
// speedup vs baseline: 3.2191x; 1.2125x over previous
#include <cuda_runtime.h>
#include <cuda_fp16.h>
#include <cstdint>

// Problem constants
#define BATCH 8
#define FIN   64
#define NPTS  4096
#define FOUT  64
#define KNN   20

#define FULLMASK 0xffffffffu
#define BIGF 3.0e38f

// ---------------------------------------------------------------------------
// Device scratch (no allocations allowed)
// ---------------------------------------------------------------------------
__device__ float g_Yt[BATCH * NPTS * FOUT];                    // W2 . x_n
__device__ float g_Ct[BATCH * NPTS * FOUT];                    // (W1-W2).x_n + b
__device__ __align__(16) float g_sq[BATCH * NPTS];             // ||x_n||^2
__device__ int   g_idx[BATCH * NPTS * KNN];                    // knn indices
__device__ __align__(16) __half g_p[BATCH * NPTS * 128];       // [hi(64)|lo(64)]

// ---------------------------------------------------------------------------
// Portable PTX helpers (compile fine for compute_103)
// ---------------------------------------------------------------------------
__device__ __forceinline__ uint32_t smem_u32(const void* p) {
    uint32_t a;
    asm("{ .reg .u64 t; cvta.to.shared.u64 t, %1; cvt.u32.u64 %0, t; }" : "=r"(a) : "l"(p));
    return a;
}
__device__ __forceinline__ void ldsm_x4(uint32_t addr, uint32_t* r) {
    asm volatile("ldmatrix.sync.aligned.m8n8.x4.shared.b16 {%0,%1,%2,%3}, [%4];"
        : "=r"(r[0]), "=r"(r[1]), "=r"(r[2]), "=r"(r[3]) : "r"(addr));
}
__device__ __forceinline__ void mma16816(float* c, const uint32_t* a, const uint32_t* b) {
    asm volatile("mma.sync.aligned.m16n8k16.row.col.f32.f16.f16.f32 "
        "{%0,%1,%2,%3}, {%4,%5,%6,%7}, {%8,%9}, {%0,%1,%2,%3};"
        : "+f"(c[0]), "+f"(c[1]), "+f"(c[2]), "+f"(c[3])
        : "r"(a[0]), "r"(a[1]), "r"(a[2]), "r"(a[3]), "r"(b[0]), "r"(b[1]));
}
__device__ __forceinline__ unsigned long long pack2(float lo, float hi) {
    unsigned long long r;
    asm("mov.b64 %0, {%1, %2};" : "=l"(r) : "f"(lo), "f"(hi));
    return r;
}
__device__ __forceinline__ void unpack2(unsigned long long v, float& lo, float& hi) {
    asm("mov.b64 {%0, %1}, %2;" : "=f"(lo), "=f"(hi) : "l"(v));
}
__device__ __forceinline__ void fma2(unsigned long long& c, unsigned long long a,
                                     unsigned long long b) {
    asm("fma.rn.f32x2 %0, %1, %2, %0;" : "+l"(c) : "l"(a), "l"(b));
}
#define CP_ASYNC16(dst, src) \
    asm volatile("cp.async.cg.shared.global [%0], [%1], 16;" :: "r"(dst), "l"(src))
#define CP_COMMIT() asm volatile("cp.async.commit_group;" ::: "memory")
#define CP_WAIT1()  asm volatile("cp.async.wait_group 1;" ::: "memory")
#define CP_WAIT0()  asm volatile("cp.async.wait_group 0;" ::: "memory")

// ---------------------------------------------------------------------------
// Kernel 1: per-point features Yt/Ct (f32x2 packed fma), sq norms, fp16 hi/lo
// ---------------------------------------------------------------------------
__global__ __launch_bounds__(128) void k1_features(
    const float* __restrict__ x, const float* __restrict__ W,
    const float* __restrict__ bvec)
{
    __shared__ float W2s[64][64];
    __shared__ float Wds[64][64];
    __shared__ float bs[64];

    const int bb  = blockIdx.y;
    const int n0  = blockIdx.x * 128;
    const int tid = threadIdx.x;

    for (int idx = tid; idx < 64 * 64; idx += 128) {
        int f = idx >> 6, o = idx & 63;
        float w1 = W[o * 128 + f];
        float w2 = W[o * 128 + 64 + f];
        W2s[f][o] = w2;
        Wds[f][o] = w1 - w2;
    }
    if (tid < 64) bs[tid] = bvec[tid];
    __syncthreads();

    const float* xb = x + (size_t)bb * FIN * NPTS;
    const int n = n0 + tid;

    float xr[64];
#pragma unroll
    for (int f = 0; f < 64; ++f) xr[f] = xb[f * NPTS + n];

    float sq = 0.f;
#pragma unroll
    for (int f = 0; f < 64; ++f) sq = fmaf(xr[f], xr[f], sq);
    g_sq[bb * NPTS + n] = sq;

    // fp16 hi/lo split pack: g_p row = [hi(64) | lo(64)]
    {
        uint4* pdst = (uint4*)(g_p + ((size_t)(bb * NPTS + n)) * 128);
#pragma unroll
        for (int q = 0; q < 8; ++q) {
            __half2 h[4];
#pragma unroll
            for (int e = 0; e < 4; ++e)
                h[e] = __floats2half2_rn(xr[q * 8 + 2 * e], xr[q * 8 + 2 * e + 1]);
            pdst[q] = make_uint4(*(unsigned*)&h[0], *(unsigned*)&h[1],
                                 *(unsigned*)&h[2], *(unsigned*)&h[3]);
        }
#pragma unroll
        for (int q = 0; q < 8; ++q) {
            float r[8];
#pragma unroll
            for (int e = 0; e < 8; ++e) {
                float xf = xr[q * 8 + e];
                r[e] = xf - __half2float(__float2half_rn(xf));
            }
            __half2 h[4];
#pragma unroll
            for (int e = 0; e < 4; ++e)
                h[e] = __floats2half2_rn(r[2 * e], r[2 * e + 1]);
            pdst[8 + q] = make_uint4(*(unsigned*)&h[0], *(unsigned*)&h[1],
                                     *(unsigned*)&h[2], *(unsigned*)&h[3]);
        }
    }

    const size_t base = ((size_t)(bb * NPTS + n)) * 64;

#pragma unroll 1
    for (int half = 0; half < 2; ++half) {
        unsigned long long ya2[16], ca2[16];
#pragma unroll
        for (int p = 0; p < 16; ++p) {
            ya2[p] = pack2(0.f, 0.f);
            ca2[p] = pack2(bs[half * 32 + 2 * p], bs[half * 32 + 2 * p + 1]);
        }

#pragma unroll 4
        for (int f = 0; f < 64; ++f) {
            const unsigned long long a2 = pack2(xr[f], xr[f]);
#pragma unroll
            for (int oo = 0; oo < 32; oo += 4) {
                float4 w2 = *(const float4*)&W2s[f][half * 32 + oo];
                float4 wd = *(const float4*)&Wds[f][half * 32 + oo];
                fma2(ya2[oo / 2],     a2, pack2(w2.x, w2.y));
                fma2(ya2[oo / 2 + 1], a2, pack2(w2.z, w2.w));
                fma2(ca2[oo / 2],     a2, pack2(wd.x, wd.y));
                fma2(ca2[oo / 2 + 1], a2, pack2(wd.z, wd.w));
            }
        }
        float4* Yp = (float4*)(g_Yt + base + half * 32);
        float4* Cp = (float4*)(g_Ct + base + half * 32);
#pragma unroll
        for (int q = 0; q < 8; ++q) {
            float y0, y1, y2, y3, c0, c1, c2, c3;
            unpack2(ya2[2 * q], y0, y1);
            unpack2(ya2[2 * q + 1], y2, y3);
            unpack2(ca2[2 * q], c0, c1);
            unpack2(ca2[2 * q + 1], c2, c3);
            Yp[q] = make_float4(y0, y1, y2, y3);
            Cp[q] = make_float4(c0, c1, c2, c3);
        }
    }
}

// ---------------------------------------------------------------------------
// Kernel 2: HMMA distance GEMM (fp16 split, 3 passes) + warp-coop top-20
// grid 256 (8 batches x 32 row-blocks of 128), 256 threads, 8 warps (4x2)
// Passes: Ah.Bh + Al.Bh + Ah.Bl   (Al.Bl ~ 2^-24, dropped)
// ---------------------------------------------------------------------------
#define TNC 64                       // candidate cols per tile
#define NT  (NPTS / TNC)             // 64 tiles
#define DSS 66                       // Ds row stride (even -> float2 aligned)

// smem byte offsets
#define SM_A   0                     // Ah[128][64] 16KB, Al[128][64] 16KB
#define SM_B   32768                 // 2 bufs x (Bh 8KB + Bl 8KB) = 32KB
#define SM_SQ  65536                 // 2 bufs x 64 floats = 512B
#define SM_D   66048                 // Ds 128 x 66 floats = 33792B
#define SM_TOT (SM_D + 128 * DSS * 4)

__global__ __launch_bounds__(256, 2) void k2_knn(void)
{
    extern __shared__ char sm[];
    const uint32_t smem_base = smem_u32(sm);
    float* Ds = (float*)(sm + SM_D);

    const int tid  = threadIdx.x;
    const int wid  = tid >> 5;
    const int lane = tid & 31;
    const int wr   = wid & 3;        // warp row group (32 rows) for GEMM
    const int wc   = wid >> 2;       // warp col group (32 cols) for GEMM

    const int bb = blockIdx.x >> 5;
    const int n0 = (blockIdx.x & 31) * 128;

    const __half* gp = g_p + (size_t)bb * NPTS * 128;

    // ---- load A panels (hi|lo) swizzled ----
    for (int idx = tid; idx < 128 * 16; idx += 256) {
        int r = idx >> 4, ch = idx & 15;
        uint4 v = *(const uint4*)(gp + (size_t)(n0 + r) * 128 + ch * 8);
        uint32_t pan = (ch < 8) ? 0u : 16384u;
        uint32_t c16 = ch & 7;
        *(uint4*)(sm + SM_A + pan + r * 128 + ((c16 ^ (r & 7)) << 4)) = v;
    }

    // ---- B tile loader (cp.async) ----
    auto loadB = [&](int t, int buf) {
        const __half* src0 = gp + (size_t)t * TNC * 128;
        uint32_t dst0 = smem_base + SM_B + buf * 16384;
#pragma unroll
        for (int k = 0; k < 4; ++k) {
            int idx = tid + k * 256;             // 0..1023
            int r = idx >> 4, ch = idx & 15;
            uint32_t pan = (ch < 8) ? 0u : 8192u;
            uint32_t c16 = ch & 7;
            CP_ASYNC16(dst0 + pan + r * 128 + ((c16 ^ (r & 7)) << 4),
                       src0 + (size_t)r * 128 + ch * 8);
        }
        if (tid < 16)
            CP_ASYNC16(smem_base + SM_SQ + buf * 256 + tid * 16,
                       g_sq + bb * NPTS + t * TNC + tid * 4);
    };

    // ---- selection state: warp owns 16 rows; list across lanes 0..19 ----
    float lv[16];
    int   li[16];
#pragma unroll
    for (int r = 0; r < 16; ++r) { lv[r] = BIGF; li[r] = 0; }
    const int srow0 = wid * 16;

    loadB(0, 0);
    CP_COMMIT();

#pragma unroll 1
    for (int t = 0; t < NT; ++t) {
        const int cur = t & 1;
        if (t + 1 < NT) { loadB(t + 1, (t + 1) & 1); CP_COMMIT(); CP_WAIT1(); }
        else            { CP_WAIT0(); }
        __syncthreads();                 // tile t resident (and A on t==0)

        // ---- GEMM: ks-outer, 3 passes share fragments ----
        float acc[2][4][4];
#pragma unroll
        for (int mt = 0; mt < 2; ++mt)
#pragma unroll
            for (int nt = 0; nt < 4; ++nt)
#pragma unroll
                for (int e = 0; e < 4; ++e) acc[mt][nt][e] = 0.f;

        const uint32_t abase = smem_base + SM_A;
        const uint32_t bbase = smem_base + SM_B + cur * 16384;
#pragma unroll
        for (int ks = 0; ks < 4; ++ks) {
            uint32_t ah[2][4], al[2][4], bh[2][4], bl[2][4];
            const int acha = ks * 2 + (lane >> 4);
            const int bcha = ks * 2 + ((lane >> 3) & 1);
#pragma unroll
            for (int mt = 0; mt < 2; ++mt) {
                int row = wr * 32 + mt * 16 + (lane & 15);
                uint32_t off = row * 128 + ((acha ^ (row & 7)) << 4);
                ldsm_x4(abase + off, ah[mt]);
                ldsm_x4(abase + 16384u + off, al[mt]);
            }
#pragma unroll
            for (int g = 0; g < 2; ++g) {
                int row = wc * 32 + g * 16 + (lane & 7) + ((lane >> 4) << 3);
                uint32_t off = row * 128 + ((bcha ^ (row & 7)) << 4);
                ldsm_x4(bbase + off, bh[g]);
                ldsm_x4(bbase + 8192u + off, bl[g]);
            }
#pragma unroll
            for (int mt = 0; mt < 2; ++mt)
#pragma unroll
                for (int nt = 0; nt < 4; ++nt)
                    mma16816(acc[mt][nt], ah[mt], &bh[nt >> 1][(nt & 1) * 2]);
#pragma unroll
            for (int mt = 0; mt < 2; ++mt)
#pragma unroll
                for (int nt = 0; nt < 4; ++nt)
                    mma16816(acc[mt][nt], al[mt], &bh[nt >> 1][(nt & 1) * 2]);
#pragma unroll
            for (int mt = 0; mt < 2; ++mt)
#pragma unroll
                for (int nt = 0; nt < 4; ++nt)
                    mma16816(acc[mt][nt], ah[mt], &bl[nt >> 1][(nt & 1) * 2]);
        }

        // ---- stage dot tile to smem (stride 66) ----
#pragma unroll
        for (int mt = 0; mt < 2; ++mt) {
            int row0 = wr * 32 + mt * 16 + (lane >> 2);
#pragma unroll
            for (int nt = 0; nt < 4; ++nt) {
                int col0 = wc * 32 + nt * 8 + 2 * (lane & 3);
                Ds[row0 * DSS + col0]           = acc[mt][nt][0];
                Ds[row0 * DSS + col0 + 1]       = acc[mt][nt][1];
                Ds[(row0 + 8) * DSS + col0]     = acc[mt][nt][2];
                Ds[(row0 + 8) * DSS + col0 + 1] = acc[mt][nt][3];
            }
        }
        __syncthreads();

        // ---- warp-cooperative top-20: paired keys, one ballot per row ----
        const float2 sqv = ((const float2*)(sm + SM_SQ + cur * 256))[lane];
        const int m0g = t * TNC + 2 * lane;       // lane's candidate pair ids
        const int m1g = m0g + 1;

#pragma unroll
        for (int r = 0; r < 16; ++r) {
            const int row   = srow0 + r;
            const int nrowr = n0 + row;
            const float2 d2 = *(const float2*)&Ds[row * DSS + 2 * lane];
            float k0 = fmaf(-2.0f, d2.x, sqv.x);
            float k1 = fmaf(-2.0f, d2.y, sqv.y);
            if (m0g == nrowr) k0 = BIGF;          // self-exclusion
            if (m1g == nrowr) k1 = BIGF;

            float w = __shfl_sync(FULLMASK, lv[r], 19);   // current worst
            unsigned b = __ballot_sync(FULLMASK, fminf(k0, k1) < w);
            while (b) {
                const int s = __ffs(b) - 1;
                b &= b - 1;
                const float K0 = __shfl_sync(FULLMASK, k0, s);
                const float K1 = __shfl_sync(FULLMASK, k1, s);
                const int   mb = t * TNC + 2 * s;
#pragma unroll
                for (int e = 0; e < 2; ++e) {
                    const float key = e ? K1 : K0;
                    if (key < w) {
                        // shuffle-shift sorted insert (ascending, lane19 worst)
                        const float vprev = __shfl_up_sync(FULLMASK, lv[r], 1);
                        const int   iprev = __shfl_up_sync(FULLMASK, li[r], 1);
                        const bool pv    = lv[r] > key;
                        const bool pprev = (lane == 0) ? false : (vprev > key);
                        lv[r] = pv ? (pprev ? vprev : key) : lv[r];
                        li[r] = pv ? (pprev ? iprev : (mb + e)) : li[r];
                        w = __shfl_sync(FULLMASK, lv[r], 19);
                    }
                }
            }
        }
        __syncthreads();                 // Ds / sq reusable
    }

    // ---- write neighbor indices ----
#pragma unroll
    for (int r = 0; r < 16; ++r) {
        const int row = srow0 + r;
        if (lane < KNN)
            g_idx[((size_t)(bb * NPTS + n0 + row)) * KNN + lane] = li[r];
    }
}

// ---------------------------------------------------------------------------
// Kernel 3: gather-max epilogue + transpose to [b][o][n]
// ---------------------------------------------------------------------------
__global__ __launch_bounds__(256) void k3_epilogue(float* __restrict__ out)
{
    __shared__ float outs[64][65];
    const int bb  = blockIdx.y;
    const int n0  = blockIdx.x * 64;
    const int tid = threadIdx.x;
    const int w    = tid >> 5;
    const int lane = tid & 31;

    const float* Y = g_Yt + (size_t)bb * NPTS * 64;
    const float* C = g_Ct + (size_t)bb * NPTS * 64;

#pragma unroll 1
    for (int s = 0; s < 8; ++s) {
        int nn = w * 8 + s;
        int n  = n0 + nn;
        int jj = 0;
        if (lane < KNN) jj = g_idx[((size_t)(bb * NPTS + n)) * KNN + lane];
        float m0v = -3.0e38f, m1v = -3.0e38f;
#pragma unroll
        for (int i = 0; i < KNN; ++i) {
            int j = __shfl_sync(0xffffffffu, jj, i);
            const float* yr = Y + (size_t)j * 64;
            m0v = fmaxf(m0v, yr[lane]);
            m1v = fmaxf(m1v, yr[lane + 32]);
        }
        outs[nn][lane]      = m0v + C[(size_t)n * 64 + lane];
        outs[nn][lane + 32] = m1v + C[(size_t)n * 64 + lane + 32];
    }
    __syncthreads();

    float* ob = out + (size_t)bb * FOUT * NPTS;
#pragma unroll
    for (int it = 0; it < 16; ++it) {
        int lin = it * 256 + tid;
        int o  = lin >> 6;
        int nn = lin & 63;
        ob[o * NPTS + n0 + nn] = outs[nn][o];
    }
}

// ---------------------------------------------------------------------------
extern "C" void kernel_launch(void* const* d_in, const int* in_sizes, int n_in,
                              void* d_out, int out_size)
{
    const float* x    = (const float*)d_in[0];
    const float* W    = (const float*)d_in[1];
    const float* bvec = (const float*)d_in[2];
    float* out        = (float*)d_out;

    cudaFuncSetAttribute(k2_knn, cudaFuncAttributeMaxDynamicSharedMemorySize, SM_TOT);

    k1_features<<<dim3(NPTS / 128, BATCH), 128>>>(x, W, bvec);
    k2_knn<<<BATCH * (NPTS / 128), 256, SM_TOT>>>();
    k3_epilogue<<<dim3(NPTS / 64, BATCH), 256>>>(out);
}